// round 1
// baseline (speedup 1.0000x reference)
#include <cuda_runtime.h>
#include <cstdint>
#include <cstddef>

#define HIDD 128

constexpr int cNP  = 100000;
constexpr int cNS  = 10000;
constexpr int cEMB = 256;
constexpr int cE   = 500000;
constexpr int cL   = 200000;

constexpr size_t SZ_P = (size_t)cNP * HIDD;   // 12.8M floats
constexpr size_t SZ_S = (size_t)cNS * HIDD;   // 1.28M floats

// scratch layout (floats)
constexpr size_t OFF_XP   = 0;
constexpr size_t OFF_HP   = OFF_XP   + SZ_P;
constexpr size_t OFF_OP   = OFF_HP   + SZ_P;
constexpr size_t OFF_AGGP = OFF_OP   + SZ_P;
constexpr size_t OFF_P1   = OFF_AGGP + SZ_P;
constexpr size_t OFF_XS   = OFF_P1   + SZ_P;
constexpr size_t OFF_HS   = OFF_XS   + SZ_S;
constexpr size_t OFF_OS   = OFF_HS   + SZ_S;
constexpr size_t OFF_AGGS = OFF_OS   + SZ_S;
constexpr size_t OFF_Y    = OFF_AGGS + SZ_S;
constexpr size_t OFF_S1   = OFF_Y    + SZ_S;
constexpr size_t OFF_DEGP = OFF_S1   + SZ_S;
constexpr size_t OFF_DEGS = OFF_DEGP + cNP;
constexpr size_t SCRATCH_TOTAL = OFF_DEGS + cNS;

__device__ float g_scratch[SCRATCH_TOTAL];

// ---------------------------------------------------------------------------
// zero a float buffer (n must be a multiple of 4)
__global__ void zero_kernel(float* __restrict__ p, int n4) {
    int i = blockIdx.x * blockDim.x + threadIdx.x;
    if (i < n4) ((float4*)p)[i] = make_float4(0.f, 0.f, 0.f, 0.f);
}

// ---------------------------------------------------------------------------
// per-node in-degree for both directions
__global__ void deg_kernel(const int* __restrict__ esrc, const int* __restrict__ edst,
                           float* __restrict__ degp, float* __restrict__ degs, int E) {
    int i = blockIdx.x * blockDim.x + threadIdx.x;
    if (i < E) {
        atomicAdd(&degp[esrc[i]], 1.f);
        atomicAdd(&degs[edst[i]], 1.f);
    }
}

// ---------------------------------------------------------------------------
// edge scatter: agg[idst[e]] += feat[isrc[e]]   (one warp per edge, red.v4)
__global__ void scatter_kernel(const float* __restrict__ feat,
                               const int* __restrict__ isrc,
                               const int* __restrict__ idst,
                               float* __restrict__ agg, int E) {
    int w    = (int)((blockIdx.x * (unsigned)blockDim.x + threadIdx.x) >> 5);
    int lane = threadIdx.x & 31;
    if (w >= E) return;
    int s = isrc[w];
    int d = idst[w];
    float4 v = *((const float4*)(feat + (size_t)s * HIDD) + lane);
    float* p = agg + (size_t)d * HIDD + lane * 4;
    asm volatile("red.global.add.v4.f32 [%0], {%1,%2,%3,%4};"
                 :: "l"(p), "f"(v.x), "f"(v.y), "f"(v.z), "f"(v.w)
                 : "memory");
}

// ---------------------------------------------------------------------------
// Generic fused GEMM, N = 128 fixed:
//   C = act( (A1 (.rowdiv degA1)) @ W1  +  A2 @ W2  + bias + addrow[idx] (.rowdiv degAdd) )
// Any of A1/A2/bias/addrow may be null. K1/K2 multiples of 16. BM=64, BN=128.
__global__ void __launch_bounds__(256)
gemm_fused(int M,
           const float* __restrict__ A1, const float* __restrict__ degA1,
           const float* __restrict__ W1, int K1,
           const float* __restrict__ A2, const float* __restrict__ W2, int K2,
           const float* __restrict__ bias,
           const float* __restrict__ addrow, const int* __restrict__ addidx,
           const float* __restrict__ degAdd,
           float* __restrict__ C, int do_relu)
{
    __shared__ float As[64][16];
    __shared__ float Wsm[16][128];

    const int tid = threadIdx.x;
    const int tx  = tid & 15;       // 8 output cols each
    const int ty  = tid >> 4;       // 4 output rows each
    const int m0  = blockIdx.x * 64;

    float acc[4][8];
#pragma unroll
    for (int i = 0; i < 4; i++)
#pragma unroll
        for (int j = 0; j < 8; j++) acc[i][j] = 0.f;

    const int lrow = tid >> 2;        // 0..63 : A-tile row this thread loads
    const int lc4  = (tid & 3) * 4;   // 0,4,8,12
    const int wkr  = tid >> 4;        // 0..15 : W-tile row
    const int wc   = (tid & 15) * 8;  // W-tile col

#pragma unroll 1
    for (int pass = 0; pass < 2; pass++) {
        const float* A = pass ? A2 : A1;
        const float* W = pass ? W2 : W1;
        const int    K = pass ? K2 : K1;
        if (A == nullptr) continue;
        const float* dg = pass ? nullptr : degA1;

        const int arow = m0 + lrow;
        float rs = 1.f;
        if (dg) rs = (arow < M) ? 1.f / fmaxf(dg[arow], 1.f) : 0.f;

        for (int k0 = 0; k0 < K; k0 += 16) {
            float4 av = make_float4(0.f, 0.f, 0.f, 0.f);
            if (arow < M) av = *(const float4*)(A + (size_t)arow * K + k0 + lc4);
            if (dg) { av.x *= rs; av.y *= rs; av.z *= rs; av.w *= rs; }
            *(float4*)&As[lrow][lc4] = av;

            float4 w0 = *(const float4*)(W + (size_t)(k0 + wkr) * HIDD + wc);
            float4 w1 = *(const float4*)(W + (size_t)(k0 + wkr) * HIDD + wc + 4);
            *(float4*)&Wsm[wkr][wc]     = w0;
            *(float4*)&Wsm[wkr][wc + 4] = w1;
            __syncthreads();

#pragma unroll
            for (int k = 0; k < 16; k++) {
                float ar[4];
#pragma unroll
                for (int i = 0; i < 4; i++) ar[i] = As[ty * 4 + i][k];
                float4 b0 = *(const float4*)&Wsm[k][tx * 8];
                float4 b1 = *(const float4*)&Wsm[k][tx * 8 + 4];
                float br[8] = {b0.x, b0.y, b0.z, b0.w, b1.x, b1.y, b1.z, b1.w};
#pragma unroll
                for (int i = 0; i < 4; i++)
#pragma unroll
                    for (int j = 0; j < 8; j++)
                        acc[i][j] = fmaf(ar[i], br[j], acc[i][j]);
            }
            __syncthreads();
        }
    }

    // epilogue
    const int c0 = tx * 8;
    float bv[8];
    if (bias) {
        float4 q0 = *(const float4*)(bias + c0);
        float4 q1 = *(const float4*)(bias + c0 + 4);
        bv[0]=q0.x; bv[1]=q0.y; bv[2]=q0.z; bv[3]=q0.w;
        bv[4]=q1.x; bv[5]=q1.y; bv[6]=q1.z; bv[7]=q1.w;
    } else {
#pragma unroll
        for (int j = 0; j < 8; j++) bv[j] = 0.f;
    }

#pragma unroll
    for (int i = 0; i < 4; i++) {
        int r = m0 + ty * 4 + i;
        if (r >= M) continue;
        float vals[8];
#pragma unroll
        for (int j = 0; j < 8; j++) vals[j] = acc[i][j] + bv[j];
        if (addrow) {
            int ridx = addidx ? addidx[r] : r;
            float s  = degAdd ? 1.f / fmaxf(degAdd[r], 1.f) : 1.f;
            const float4* ap = (const float4*)(addrow + (size_t)ridx * HIDD + c0);
            float4 a0 = ap[0], a1 = ap[1];
            vals[0] = fmaf(a0.x, s, vals[0]);
            vals[1] = fmaf(a0.y, s, vals[1]);
            vals[2] = fmaf(a0.z, s, vals[2]);
            vals[3] = fmaf(a0.w, s, vals[3]);
            vals[4] = fmaf(a1.x, s, vals[4]);
            vals[5] = fmaf(a1.y, s, vals[5]);
            vals[6] = fmaf(a1.z, s, vals[6]);
            vals[7] = fmaf(a1.w, s, vals[7]);
        }
        if (do_relu) {
#pragma unroll
            for (int j = 0; j < 8; j++) vals[j] = fmaxf(vals[j], 0.f);
        }
        float4 o0 = make_float4(vals[0], vals[1], vals[2], vals[3]);
        float4 o1 = make_float4(vals[4], vals[5], vals[6], vals[7]);
        *(float4*)(C + (size_t)r * HIDD + c0)     = o0;
        *(float4*)(C + (size_t)r * HIDD + c0 + 4) = o1;
    }
}

// ---------------------------------------------------------------------------
// label classifier: out[l] = relu(P1[lp[l]] + S1[ls[l]]) . Wc2 + bc2
// (bc1 already folded into S1). One warp per label.
__global__ void label_kernel(const float* __restrict__ P1, const float* __restrict__ S1,
                             const int* __restrict__ lp, const int* __restrict__ ls,
                             const float* __restrict__ Wc2, const float* __restrict__ bc2,
                             float* __restrict__ out, int L) {
    int w    = (int)((blockIdx.x * (unsigned)blockDim.x + threadIdx.x) >> 5);
    int lane = threadIdx.x & 31;
    if (w >= L) return;
    int ip = lp[w];
    int is = ls[w];
    float4 a  = *((const float4*)(P1 + (size_t)ip * HIDD) + lane);
    float4 b  = *((const float4*)(S1 + (size_t)is * HIDD) + lane);
    float4 wv = *((const float4*)Wc2 + lane);
    float acc = fmaxf(a.x + b.x, 0.f) * wv.x
              + fmaxf(a.y + b.y, 0.f) * wv.y
              + fmaxf(a.z + b.z, 0.f) * wv.z
              + fmaxf(a.w + b.w, 0.f) * wv.w;
#pragma unroll
    for (int off = 16; off > 0; off >>= 1)
        acc += __shfl_xor_sync(0xffffffffu, acc, off);
    if (lane == 0) out[w] = acc + bc2[0];
}

// ---------------------------------------------------------------------------
extern "C" void kernel_launch(void* const* d_in, const int* in_sizes, int n_in,
                              void* d_out, int out_size) {
    (void)in_sizes; (void)n_in; (void)out_size;

    const float* x_paper     = (const float*)d_in[0];
    const float* x_software  = (const float*)d_in[1];
    const int*   paper_id    = (const int*)d_in[2];
    const int*   software_id = (const int*)d_in[3];
    const int*   edge_src    = (const int*)d_in[4];
    const int*   edge_dst    = (const int*)d_in[5];
    const int*   lbl_paper   = (const int*)d_in[6];
    const int*   lbl_soft    = (const int*)d_in[7];
    const float* paper_emb   = (const float*)d_in[8];
    const float* soft_emb    = (const float*)d_in[9];
    const float* Wp     = (const float*)d_in[10];
    const float* bp     = (const float*)d_in[11];
    const float* Ws_in  = (const float*)d_in[12];
    const float* bs     = (const float*)d_in[13];
    const float* Wl1_ps = (const float*)d_in[14];
    const float* bl1_ps = (const float*)d_in[15];
    const float* Wr1_ps = (const float*)d_in[16];
    const float* Wl1_sp = (const float*)d_in[17];
    const float* bl1_sp = (const float*)d_in[18];
    const float* Wr1_sp = (const float*)d_in[19];
    const float* Wl2_ps = (const float*)d_in[20];
    const float* bl2_ps = (const float*)d_in[21];
    const float* Wr2_ps = (const float*)d_in[22];
    const float* Wl2_sp = (const float*)d_in[23];
    const float* bl2_sp = (const float*)d_in[24];
    const float* Wr2_sp = (const float*)d_in[25];
    const float* Wc1    = (const float*)d_in[26];
    const float* bc1    = (const float*)d_in[27];
    const float* Wc2    = (const float*)d_in[28];
    const float* bc2    = (const float*)d_in[29];
    float* out = (float*)d_out;

    float* scratch = nullptr;
    cudaGetSymbolAddress((void**)&scratch, g_scratch);
    float* xp   = scratch + OFF_XP;
    float* hp   = scratch + OFF_HP;
    float* op   = scratch + OFF_OP;
    float* aggP = scratch + OFF_AGGP;
    float* P1   = scratch + OFF_P1;
    float* xs   = scratch + OFF_XS;
    float* hs   = scratch + OFF_HS;
    float* os   = scratch + OFF_OS;
    float* aggS = scratch + OFF_AGGS;
    float* yb   = scratch + OFF_Y;
    float* S1   = scratch + OFF_S1;
    float* degp = scratch + OFF_DEGP;
    float* degs = scratch + OFF_DEGS;

    const int T = 256;
    auto blocksZ = [](size_t nfloats) { return (int)((nfloats / 4 + 255) / 256); };
    const int gP = (cNP + 63) / 64;
    const int gS = (cNS + 63) / 64;
    const int gE = (cE + 7) / 8;      // one warp per edge, 8 warps/block
    const int gL = (cL + 7) / 8;

    // degrees
    zero_kernel<<<blocksZ(cNP), T>>>(degp, cNP / 4);
    zero_kernel<<<blocksZ(cNS), T>>>(degs, cNS / 4);
    deg_kernel<<<(cE + T - 1) / T, T>>>(edge_src, edge_dst, degp, degs, cE);

    // input fusion: x = X @ W + b + emb[id]
    gemm_fused<<<gP, T>>>(cNP, x_paper, nullptr, Wp, cEMB,
                          nullptr, nullptr, 0, bp,
                          paper_emb, paper_id, nullptr, xp, 0);
    gemm_fused<<<gS, T>>>(cNS, x_software, nullptr, Ws_in, cEMB,
                          nullptr, nullptr, 0, bs,
                          soft_emb, software_id, nullptr, xs, 0);

    // layer 1, paper -> software:  h_s = relu(mean_agg(xp)@Wl1_ps + bl1_ps + xs@Wr1_ps)
    zero_kernel<<<blocksZ(SZ_S), T>>>(aggS, (int)(SZ_S / 4));
    scatter_kernel<<<gE, T>>>(xp, edge_src, edge_dst, aggS, cE);
    gemm_fused<<<gS, T>>>(cNS, aggS, degs, Wl1_ps, HIDD,
                          xs, Wr1_ps, HIDD, bl1_ps,
                          nullptr, nullptr, nullptr, hs, 1);

    // layer 1, software -> paper (pre-transform: mean commutes with linear)
    gemm_fused<<<gS, T>>>(cNS, xs, nullptr, Wl1_sp, HIDD,
                          nullptr, nullptr, 0, nullptr,
                          nullptr, nullptr, nullptr, yb, 0);
    zero_kernel<<<blocksZ(SZ_P), T>>>(aggP, (int)(SZ_P / 4));
    scatter_kernel<<<gE, T>>>(yb, edge_dst, edge_src, aggP, cE);
    gemm_fused<<<gP, T>>>(cNP, xp, nullptr, Wr1_sp, HIDD,
                          nullptr, nullptr, 0, bl1_sp,
                          aggP, nullptr, degp, hp, 1);

    // layer 2, paper -> software (no relu)
    zero_kernel<<<blocksZ(SZ_S), T>>>(aggS, (int)(SZ_S / 4));
    scatter_kernel<<<gE, T>>>(hp, edge_src, edge_dst, aggS, cE);
    gemm_fused<<<gS, T>>>(cNS, aggS, degs, Wl2_ps, HIDD,
                          hs, Wr2_ps, HIDD, bl2_ps,
                          nullptr, nullptr, nullptr, os, 0);

    // layer 2, software -> paper (no relu)
    gemm_fused<<<gS, T>>>(cNS, hs, nullptr, Wl2_sp, HIDD,
                          nullptr, nullptr, 0, nullptr,
                          nullptr, nullptr, nullptr, yb, 0);
    zero_kernel<<<blocksZ(SZ_P), T>>>(aggP, (int)(SZ_P / 4));
    scatter_kernel<<<gE, T>>>(yb, edge_dst, edge_src, aggP, cE);
    gemm_fused<<<gP, T>>>(cNP, hp, nullptr, Wr2_sp, HIDD,
                          nullptr, nullptr, 0, bl2_sp,
                          aggP, nullptr, degp, op, 0);

    // classifier restructure: P1 = op @ Wc1[:128], S1 = os @ Wc1[128:] + bc1
    gemm_fused<<<gP, T>>>(cNP, op, nullptr, Wc1, HIDD,
                          nullptr, nullptr, 0, nullptr,
                          nullptr, nullptr, nullptr, P1, 0);
    gemm_fused<<<gS, T>>>(cNS, os, nullptr, Wc1 + 128 * HIDD, HIDD,
                          nullptr, nullptr, 0, bc1,
                          nullptr, nullptr, nullptr, S1, 0);

    // per-label gather + relu + dot
    label_kernel<<<gL, T>>>(P1, S1, lbl_paper, lbl_soft, Wc2, bc2, out, cL);
}

// round 17
// speedup vs baseline: 1.2123x; 1.2123x over previous
#include <cuda_runtime.h>
#include <cstdint>
#include <cstddef>

#define HIDD 128

constexpr int cNP  = 100000;
constexpr int cNS  = 10000;
constexpr int cEMB = 256;
constexpr int cE   = 500000;
constexpr int cL   = 200000;

constexpr size_t SZ_P = (size_t)cNP * HIDD;
constexpr size_t SZ_S = (size_t)cNS * HIDD;

constexpr size_t OFF_XP   = 0;
constexpr size_t OFF_HP   = OFF_XP   + SZ_P;
constexpr size_t OFF_OP   = OFF_HP   + SZ_P;
constexpr size_t OFF_AGGP = OFF_OP   + SZ_P;
constexpr size_t OFF_P1   = OFF_AGGP + SZ_P;
constexpr size_t OFF_XS   = OFF_P1   + SZ_P;
constexpr size_t OFF_HS   = OFF_XS   + SZ_S;
constexpr size_t OFF_OS   = OFF_HS   + SZ_S;
constexpr size_t OFF_AGGS = OFF_OS   + SZ_S;
constexpr size_t OFF_Y    = OFF_AGGS + SZ_S;
constexpr size_t OFF_S1   = OFF_Y    + SZ_S;
constexpr size_t OFF_DEGP = OFF_S1   + SZ_S;
constexpr size_t OFF_DEGS = OFF_DEGP + cNP;
constexpr size_t SCRATCH_TOTAL = OFF_DEGS + cNS;

__device__ float g_scratch[SCRATCH_TOTAL];

// ---------------------------------------------------------------------------
// zero a float buffer (n4 = count of float4s)
__global__ void zero_kernel(float* __restrict__ p, int n4) {
    int i = blockIdx.x * blockDim.x + threadIdx.x;
    if (i < n4) ((float4*)p)[i] = make_float4(0.f, 0.f, 0.f, 0.f);
}

// ---------------------------------------------------------------------------
// per-node in-degree for both edge directions
__global__ void deg_kernel(const int* __restrict__ esrc, const int* __restrict__ edst,
                           float* __restrict__ degp, float* __restrict__ degs, int E) {
    int i = blockIdx.x * blockDim.x + threadIdx.x;
    if (i < E) {
        atomicAdd(&degp[esrc[i]], 1.f);
        atomicAdd(&degs[edst[i]], 1.f);
    }
}

// ---------------------------------------------------------------------------
// edge scatter: agg[idst[e]] += feat[isrc[e]]   (one warp per edge, red.v4)
__global__ void scatter_kernel(const float* __restrict__ feat,
                               const int* __restrict__ isrc,
                               const int* __restrict__ idst,
                               float* __restrict__ agg, int E) {
    int w    = (int)((blockIdx.x * (unsigned)blockDim.x + threadIdx.x) >> 5);
    int lane = threadIdx.x & 31;
    if (w >= E) return;
    int s = isrc[w];
    int d = idst[w];
    float4 v = *((const float4*)(feat + (size_t)s * HIDD) + lane);
    float* p = agg + (size_t)d * HIDD + lane * 4;
    asm volatile("red.global.add.v4.f32 [%0], {%1,%2,%3,%4};"
                 :: "l"(p), "f"(v.x), "f"(v.y), "f"(v.z), "f"(v.w)
                 : "memory");
}

// ---------------------------------------------------------------------------
// FFMA fused GEMM, N = 128 fixed:
//   C = act( (A1 .rowdiv degA1) @ W1 + A2 @ W2 + bias + addrow[idx] .rowdiv degAdd )
// 128x128 tile, 8x8 register blocking per thread (256 threads).
// A staged k-major in SMEM so the inner loop is 4x LDS.128 per 64 FFMA:
//   - As[k][row] reads are warp-broadcast across the 16 tx lanes (free)
//   - Ws[k][n] reads are 32B-strided (at worst 2-way conflicted)
// K1/K2 must be multiples of 16; any of A1/A2/bias/addrow may be null.
// ---------------------------------------------------------------------------
__global__ void __launch_bounds__(256)
gemm_ffma(int M,
          const float* __restrict__ A1, const float* __restrict__ degA1,
          const float* __restrict__ W1, int K1,
          const float* __restrict__ A2, const float* __restrict__ W2, int K2,
          const float* __restrict__ bias,
          const float* __restrict__ addrow, const int* __restrict__ addidx,
          const float* __restrict__ degAdd,
          float* __restrict__ C, int do_relu)
{
    __shared__ float As[16][128];   // k-major: As[k][m]
    __shared__ float Ws[16][128];   // Ws[k][n]

    const int tid = threadIdx.x;
    const int tx  = tid & 15;       // 8 output cols each
    const int ty  = tid >> 4;       // 8 output rows each
    const int m0  = blockIdx.x * 128;

    float acc[8][8];
#pragma unroll
    for (int i = 0; i < 8; i++)
#pragma unroll
        for (int j = 0; j < 8; j++) acc[i][j] = 0.f;

#pragma unroll 1
    for (int pass = 0; pass < 2; pass++) {
        const float* A  = pass ? A2 : A1;
        const float* W  = pass ? W2 : W1;
        const int    K  = pass ? K2 : K1;
        const float* dg = pass ? nullptr : degA1;
        if (A == nullptr) continue;

#pragma unroll 1
        for (int k0 = 0; k0 < K; k0 += 16) {
            __syncthreads();
            // stage A (transpose to k-major), 512 float4 loads
#pragma unroll
            for (int it = 0; it < 2; it++) {
                int idx = tid + it * 256;
                int row = idx >> 2;          // 0..127
                int q   = idx & 3;           // k-float4 index
                int arow = m0 + row;
                float4 v = make_float4(0.f, 0.f, 0.f, 0.f);
                if (arow < M) {
                    v = *(const float4*)(A + (size_t)arow * K + k0 + q * 4);
                    if (dg) {
                        float rs = 1.f / fmaxf(dg[arow], 1.f);
                        v.x *= rs; v.y *= rs; v.z *= rs; v.w *= rs;
                    }
                }
                As[q * 4 + 0][row] = v.x;
                As[q * 4 + 1][row] = v.y;
                As[q * 4 + 2][row] = v.z;
                As[q * 4 + 3][row] = v.w;
            }
            // stage W (n-contiguous), 512 float4 loads
#pragma unroll
            for (int it = 0; it < 2; it++) {
                int idx = tid + it * 256;
                int k   = idx >> 5;          // 0..15
                int n4  = idx & 31;          // float4 col index
                *(float4*)&Ws[k][n4 * 4] =
                    *(const float4*)(W + (size_t)(k0 + k) * HIDD + n4 * 4);
            }
            __syncthreads();

#pragma unroll
            for (int k = 0; k < 16; k++) {
                float4 a0 = *(const float4*)&As[k][ty * 8];
                float4 a1 = *(const float4*)&As[k][ty * 8 + 4];
                float4 b0 = *(const float4*)&Ws[k][tx * 8];
                float4 b1 = *(const float4*)&Ws[k][tx * 8 + 4];
                float ar[8] = {a0.x, a0.y, a0.z, a0.w, a1.x, a1.y, a1.z, a1.w};
                float br[8] = {b0.x, b0.y, b0.z, b0.w, b1.x, b1.y, b1.z, b1.w};
#pragma unroll
                for (int i = 0; i < 8; i++)
#pragma unroll
                    for (int j = 0; j < 8; j++)
                        acc[i][j] = fmaf(ar[i], br[j], acc[i][j]);
            }
        }
    }

    // epilogue
    const int c0 = tx * 8;
    float bv[8];
    if (bias) {
        float4 q0 = *(const float4*)(bias + c0);
        float4 q1 = *(const float4*)(bias + c0 + 4);
        bv[0]=q0.x; bv[1]=q0.y; bv[2]=q0.z; bv[3]=q0.w;
        bv[4]=q1.x; bv[5]=q1.y; bv[6]=q1.z; bv[7]=q1.w;
    } else {
#pragma unroll
        for (int j = 0; j < 8; j++) bv[j] = 0.f;
    }

#pragma unroll
    for (int i = 0; i < 8; i++) {
        int r = m0 + ty * 8 + i;
        if (r >= M) continue;
        float vals[8];
#pragma unroll
        for (int j = 0; j < 8; j++) vals[j] = acc[i][j] + bv[j];
        if (addrow) {
            int ridx = addidx ? addidx[r] : r;
            float s  = degAdd ? 1.f / fmaxf(degAdd[r], 1.f) : 1.f;
            const float4* ap = (const float4*)(addrow + (size_t)ridx * HIDD + c0);
            float4 a0 = ap[0], a1 = ap[1];
            vals[0] = fmaf(a0.x, s, vals[0]);
            vals[1] = fmaf(a0.y, s, vals[1]);
            vals[2] = fmaf(a0.z, s, vals[2]);
            vals[3] = fmaf(a0.w, s, vals[3]);
            vals[4] = fmaf(a1.x, s, vals[4]);
            vals[5] = fmaf(a1.y, s, vals[5]);
            vals[6] = fmaf(a1.z, s, vals[6]);
            vals[7] = fmaf(a1.w, s, vals[7]);
        }
        if (do_relu) {
#pragma unroll
            for (int j = 0; j < 8; j++) vals[j] = fmaxf(vals[j], 0.f);
        }
        *(float4*)(C + (size_t)r * HIDD + c0)     = make_float4(vals[0], vals[1], vals[2], vals[3]);
        *(float4*)(C + (size_t)r * HIDD + c0 + 4) = make_float4(vals[4], vals[5], vals[6], vals[7]);
    }
}

// ---------------------------------------------------------------------------
// label classifier: out[l] = relu(P1[lp[l]] + S1[ls[l]]) . Wc2 + bc2
// (bc1 folded into S1). One warp per label.
__global__ void label_kernel(const float* __restrict__ P1, const float* __restrict__ S1,
                             const int* __restrict__ lp, const int* __restrict__ ls,
                             const float* __restrict__ Wc2, const float* __restrict__ bc2,
                             float* __restrict__ out, int L) {
    int w    = (int)((blockIdx.x * (unsigned)blockDim.x + threadIdx.x) >> 5);
    int lane = threadIdx.x & 31;
    if (w >= L) return;
    int ip = lp[w];
    int is = ls[w];
    float4 a  = *((const float4*)(P1 + (size_t)ip * HIDD) + lane);
    float4 b  = *((const float4*)(S1 + (size_t)is * HIDD) + lane);
    float4 wv = *((const float4*)Wc2 + lane);
    float acc = fmaxf(a.x + b.x, 0.f) * wv.x
              + fmaxf(a.y + b.y, 0.f) * wv.y
              + fmaxf(a.z + b.z, 0.f) * wv.z
              + fmaxf(a.w + b.w, 0.f) * wv.w;
#pragma unroll
    for (int off = 16; off > 0; off >>= 1)
        acc += __shfl_xor_sync(0xffffffffu, acc, off);
    if (lane == 0) out[w] = acc + bc2[0];
}

// ---------------------------------------------------------------------------
extern "C" void kernel_launch(void* const* d_in, const int* in_sizes, int n_in,
                              void* d_out, int out_size) {
    (void)in_sizes; (void)n_in; (void)out_size;

    const float* x_paper     = (const float*)d_in[0];
    const float* x_software  = (const float*)d_in[1];
    const int*   paper_id    = (const int*)d_in[2];
    const int*   software_id = (const int*)d_in[3];
    const int*   edge_src    = (const int*)d_in[4];
    const int*   edge_dst    = (const int*)d_in[5];
    const int*   lbl_paper   = (const int*)d_in[6];
    const int*   lbl_soft    = (const int*)d_in[7];
    const float* paper_emb   = (const float*)d_in[8];
    const float* soft_emb    = (const float*)d_in[9];
    const float* Wp     = (const float*)d_in[10];
    const float* bp     = (const float*)d_in[11];
    const float* Ws_in  = (const float*)d_in[12];
    const float* bs     = (const float*)d_in[13];
    const float* Wl1_ps = (const float*)d_in[14];
    const float* bl1_ps = (const float*)d_in[15];
    const float* Wr1_ps = (const float*)d_in[16];
    const float* Wl1_sp = (const float*)d_in[17];
    const float* bl1_sp = (const float*)d_in[18];
    const float* Wr1_sp = (const float*)d_in[19];
    const float* Wl2_ps = (const float*)d_in[20];
    const float* bl2_ps = (const float*)d_in[21];
    const float* Wr2_ps = (const float*)d_in[22];
    const float* Wl2_sp = (const float*)d_in[23];
    const float* bl2_sp = (const float*)d_in[24];
    const float* Wr2_sp = (const float*)d_in[25];
    const float* Wc1    = (const float*)d_in[26];
    const float* bc1    = (const float*)d_in[27];
    const float* Wc2    = (const float*)d_in[28];
    const float* bc2    = (const float*)d_in[29];
    float* out = (float*)d_out;

    float* scratch = nullptr;
    cudaGetSymbolAddress((void**)&scratch, g_scratch);
    float* xp   = scratch + OFF_XP;
    float* hp   = scratch + OFF_HP;
    float* op   = scratch + OFF_OP;
    float* aggP = scratch + OFF_AGGP;
    float* P1   = scratch + OFF_P1;
    float* xs   = scratch + OFF_XS;
    float* hs   = scratch + OFF_HS;
    float* os   = scratch + OFF_OS;
    float* aggS = scratch + OFF_AGGS;
    float* yb   = scratch + OFF_Y;
    float* S1   = scratch + OFF_S1;
    float* degp = scratch + OFF_DEGP;
    float* degs = scratch + OFF_DEGS;

    const int T = 256;
    auto blocksZ = [](size_t nfloats) { return (int)((nfloats / 4 + 255) / 256); };
    const int gP = (cNP + 127) / 128;   // 782
    const int gS = (cNS + 127) / 128;   // 79
    const int gE = (cE + 7) / 8;        // one warp per edge
    const int gL = (cL + 7) / 8;

    // degrees
    zero_kernel<<<blocksZ(cNP), T>>>(degp, cNP / 4);
    zero_kernel<<<blocksZ(cNS), T>>>(degs, cNS / 4);
    deg_kernel<<<(cE + T - 1) / T, T>>>(edge_src, edge_dst, degp, degs, cE);

    // input fusion: x = X @ W + b + emb[id]
    gemm_ffma<<<gP, T>>>(cNP, x_paper, nullptr, Wp, cEMB,
                         nullptr, nullptr, 0, bp,
                         paper_emb, paper_id, nullptr, xp, 0);
    gemm_ffma<<<gS, T>>>(cNS, x_software, nullptr, Ws_in, cEMB,
                         nullptr, nullptr, 0, bs,
                         soft_emb, software_id, nullptr, xs, 0);

    // layer 1, paper -> software: h_s = relu(mean_agg(xp)@Wl1_ps + bl1_ps + xs@Wr1_ps)
    zero_kernel<<<blocksZ(SZ_S), T>>>(aggS, (int)(SZ_S / 4));
    scatter_kernel<<<gE, T>>>(xp, edge_src, edge_dst, aggS, cE);
    gemm_ffma<<<gS, T>>>(cNS, aggS, degs, Wl1_ps, HIDD,
                         xs, Wr1_ps, HIDD, bl1_ps,
                         nullptr, nullptr, nullptr, hs, 1);

    // layer 1, software -> paper (mean commutes with linear: transform 10k rows, then scatter)
    gemm_ffma<<<gS, T>>>(cNS, xs, nullptr, Wl1_sp, HIDD,
                         nullptr, nullptr, 0, nullptr,
                         nullptr, nullptr, nullptr, yb, 0);
    zero_kernel<<<blocksZ(SZ_P), T>>>(aggP, (int)(SZ_P / 4));
    scatter_kernel<<<gE, T>>>(yb, edge_dst, edge_src, aggP, cE);
    gemm_ffma<<<gP, T>>>(cNP, xp, nullptr, Wr1_sp, HIDD,
                         nullptr, nullptr, 0, bl1_sp,
                         aggP, nullptr, degp, hp, 1);

    // layer 2, paper -> software (no relu)
    zero_kernel<<<blocksZ(SZ_S), T>>>(aggS, (int)(SZ_S / 4));
    scatter_kernel<<<gE, T>>>(hp, edge_src, edge_dst, aggS, cE);
    gemm_ffma<<<gS, T>>>(cNS, aggS, degs, Wl2_ps, HIDD,
                         hs, Wr2_ps, HIDD, bl2_ps,
                         nullptr, nullptr, nullptr, os, 0);

    // layer 2, software -> paper (no relu)
    gemm_ffma<<<gS, T>>>(cNS, hs, nullptr, Wl2_sp, HIDD,
                         nullptr, nullptr, 0, nullptr,
                         nullptr, nullptr, nullptr, yb, 0);
    zero_kernel<<<blocksZ(SZ_P), T>>>(aggP, (int)(SZ_P / 4));
    scatter_kernel<<<gE, T>>>(yb, edge_dst, edge_src, aggP, cE);
    gemm_ffma<<<gP, T>>>(cNP, hp, nullptr, Wr2_sp, HIDD,
                         nullptr, nullptr, 0, bl2_sp,
                         aggP, nullptr, degp, op, 0);

    // classifier restructure: P1 = op @ Wc1[:128], S1 = os @ Wc1[128:] + bc1
    gemm_ffma<<<gP, T>>>(cNP, op, nullptr, Wc1, HIDD,
                         nullptr, nullptr, 0, nullptr,
                         nullptr, nullptr, nullptr, P1, 0);
    gemm_ffma<<<gS, T>>>(cNS, os, nullptr, Wc1 + 128 * HIDD, HIDD,
                         nullptr, nullptr, 0, bc1,
                         nullptr, nullptr, nullptr, S1, 0);

    // per-label gather + relu + dot
    label_kernel<<<gL, T>>>(P1, S1, lbl_paper, lbl_soft, Wc2, bc2, out, cL);
}